// round 3
// baseline (speedup 1.0000x reference)
#include <cuda_runtime.h>

#define H   64
#define G   256    // 4*H
#define F   5
#define BS  14     // samples per block (grid=293 <= 296 CTA slots @occ2 -> single wave)
#define TPB 128    // 2 gate rows per thread
#define RB  128    // rank-loss reduce blocks
#define CPT (BS * H / TPB)   // cells per thread in phase 2 = 7

__device__ float g_rank_part[RB];
__device__ float g_reg_part[2];

// MUFU.TANH (sm_75+): 1 MUFU op
__device__ __forceinline__ float tanh_hw(float x) {
    float y;
    asm("tanh.approx.f32 %0, %1;" : "=f"(y) : "f"(x));
    return y;
}
__device__ __forceinline__ float sig_hw(float x) {
    return fmaf(tanh_hw(0.5f * x), 0.5f, 0.5f);
}

// packed dual-FMA (sm_103a FFMA2), k-packed pairs
__device__ __forceinline__ unsigned long long fma2(unsigned long long a,
                                                   unsigned long long b,
                                                   unsigned long long c) {
    unsigned long long d;
    asm("fma.rn.f32x2 %0, %1, %2, %3;" : "=l"(d) : "l"(a), "l"(b), "l"(c));
    return d;
}
__device__ __forceinline__ float f2lo(unsigned long long v) {
    return __uint_as_float((unsigned)(v & 0xffffffffULL));
}
__device__ __forceinline__ float f2hi(unsigned long long v) {
    return __uint_as_float((unsigned)(v >> 32));
}

__global__ __launch_bounds__(TPB, 2)
void lstm_kernel(const float* __restrict__ feature,
                 const float* __restrict__ Wih, const float* __restrict__ Whh,
                 const float* __restrict__ bih, const float* __restrict__ bhh,
                 const float* __restrict__ Wd,  const float* __restrict__ bd,
                 float* __restrict__ pred, int N, int T)
{
    const int r  = threadIdx.x;          // owns gate rows 2r and 2r+1
    const int n0 = blockIdx.x * BS;
    const int r0 = 2 * r, r1 = 2 * r + 1;

    // Two rows of Whh resident, k-packed as f32x2 (128 regs)
    unsigned long long wa[H / 2], wb[H / 2];
    {
        const ulonglong2* pa = (const ulonglong2*)(Whh + r0 * H);
        const ulonglong2* pb = (const ulonglong2*)(Whh + r1 * H);
#pragma unroll
        for (int q = 0; q < H / 4; q++) {
            ulonglong2 va = pa[q], vb = pb[q];
            wa[2 * q] = va.x; wa[2 * q + 1] = va.y;
            wb[2 * q] = vb.x; wb[2 * q + 1] = vb.y;
        }
    }
    float wi0[F], wi1[F];
#pragma unroll
    for (int f = 0; f < F; f++) { wi0[f] = Wih[r0 * F + f]; wi1[f] = Wih[r1 * F + f]; }
    const float bias0 = bih[r0] + bhh[r0];
    const float bias1 = bih[r1] + bhh[r1];

    __shared__ __align__(16) float h_sm[BS][H];
    __shared__ float g_sm[BS][G];
    __shared__ float x_sm[2][BS][F];

    float c_reg[CPT];
#pragma unroll
    for (int u = 0; u < CPT; u++) {
        c_reg[u] = 0.f;
        int idx = r + TPB * u;
        h_sm[idx >> 6][idx & 63] = 0.f;
    }
    if (r < BS * F) { int s = r / F, f = r % F; x_sm[0][s][f] = 0.f; x_sm[1][s][f] = 0.f; }
    __syncthreads();
    if (r < BS * F) {
        int s = r / F, f = r % F;
        if (n0 + s < N) x_sm[0][s][f] = feature[(size_t)(n0 + s) * T * F + f];
    }
    __syncthreads();

    for (int t = 0; t < T; t++) {
        const int buf = t & 1;

        // ---- phase 1: two gate rows per thread; one LDS.128 feeds 4 FFMA2
#pragma unroll 2
        for (int s = 0; s < BS; s++) {
            const ulonglong2* h2 = (const ulonglong2*)h_sm[s];   // uniform -> broadcast
            unsigned long long a0 = 0ULL, a1 = 0ULL;
#pragma unroll
            for (int q = 0; q < H / 4; q++) {
                ulonglong2 hv = h2[q];
                a0 = fma2(wa[2 * q],     hv.x, a0);
                a1 = fma2(wb[2 * q],     hv.x, a1);
                a0 = fma2(wa[2 * q + 1], hv.y, a0);
                a1 = fma2(wb[2 * q + 1], hv.y, a1);
            }
            float v0 = f2lo(a0) + f2hi(a0) + bias0;
            float v1 = f2lo(a1) + f2hi(a1) + bias1;
#pragma unroll
            for (int f = 0; f < F; f++) {
                float xv = x_sm[buf][s][f];
                v0 = fmaf(wi0[f], xv, v0);
                v1 = fmaf(wi1[f], xv, v1);
            }
            *(float2*)&g_sm[s][r0] = make_float2(v0, v1);   // STS.64, conflict-free
        }
        __syncthreads();

        // ---- prefetch x for t+1
        if (t + 1 < T && r < BS * F) {
            int s = r / F, f = r % F;
            if (n0 + s < N)
                x_sm[buf ^ 1][s][f] =
                    feature[(size_t)(n0 + s) * T * F + (size_t)(t + 1) * F + f];
        }

        // ---- phase 2: LSTM cell update (gate order i,f,g,o)
#pragma unroll
        for (int u = 0; u < CPT; u++) {
            int idx = r + TPB * u;
            int s = idx >> 6, j = idx & 63;
            float ig = sig_hw(g_sm[s][j]);
            float fg = sig_hw(g_sm[s][H + j]);
            float gg = tanh_hw(g_sm[s][2 * H + j]);
            float og = sig_hw(g_sm[s][3 * H + j]);
            float c  = fg * c_reg[u] + ig * gg;
            c_reg[u] = c;
            h_sm[s][j] = og * tanh_hw(c);
        }
        __syncthreads();
    }

    // ---- head: pred = leaky_relu(h . Wd + bd, 0.2); warp-strided over samples
    int w = r >> 5, lane = r & 31;
    for (int s = w; s < BS; s += TPB / 32) {
        if (n0 + s < N) {
            float p = h_sm[s][lane] * Wd[lane] + h_sm[s][lane + 32] * Wd[lane + 32];
#pragma unroll
            for (int off = 16; off; off >>= 1) p += __shfl_down_sync(0xffffffffu, p, off);
            if (lane == 0) {
                p += bd[0];
                p = p > 0.f ? p : 0.2f * p;
                pred[n0 + s] = p;
            }
        }
    }
}

// Pairwise rank loss partials + masked MSE partials (deterministic, no atomics).
__global__ void pair_kernel(const float* __restrict__ pred, const float* __restrict__ ret,
                            const unsigned* __restrict__ mask, int N)
{
    __shared__ float p_sm[4096];
    __shared__ float t_sm[4096];
    __shared__ unsigned char m_sm[4096];
    __shared__ float red[256];
    const int tid = threadIdx.x;

    for (int n = tid; n < N; n += blockDim.x) {
        p_sm[n] = pred[n];
        t_sm[n] = ret[n];
        m_sm[n] = (mask[n] != 0u) ? 1 : 0;
    }
    __syncthreads();

    float rsum = 0.f;
    for (int i = blockIdx.x; i < N; i += gridDim.x) {
        if (!m_sm[i]) continue;
        float pi = p_sm[i], gi = t_sm[i];
        for (int j = tid; j < N; j += blockDim.x) {
            float v = -(p_sm[j] - pi) * (t_sm[j] - gi);
            v = fmaxf(v, 0.f);
            rsum += v * (float)m_sm[j];
        }
    }
    red[tid] = rsum;
    __syncthreads();
    for (int s = 128; s; s >>= 1) { if (tid < s) red[tid] += red[tid + s]; __syncthreads(); }
    if (tid == 0) g_rank_part[blockIdx.x] = red[0];

    if (blockIdx.x == 0) {
        float ssq = 0.f, sm = 0.f;
        for (int n = tid; n < N; n += blockDim.x) {
            float m = (float)m_sm[n];
            float d = p_sm[n] - t_sm[n];
            ssq += d * d * m;
            sm  += m;
        }
        __syncthreads();
        red[tid] = ssq; __syncthreads();
        for (int s = 128; s; s >>= 1) { if (tid < s) red[tid] += red[tid + s]; __syncthreads(); }
        if (tid == 0) g_reg_part[0] = red[0];
        __syncthreads();
        red[tid] = sm; __syncthreads();
        for (int s = 128; s; s >>= 1) { if (tid < s) red[tid] += red[tid + s]; __syncthreads(); }
        if (tid == 0) g_reg_part[1] = red[0];
    }
}

__global__ void finalize_kernel(float* __restrict__ out, int N)
{
    if (threadIdx.x == 0 && blockIdx.x == 0) {
        float srank = 0.f;
        for (int b = 0; b < RB; b++) srank += g_rank_part[b];
        float reg  = g_reg_part[0] / (g_reg_part[1] + 1e-8f);
        float rank = srank / ((float)N * (float)N);
        out[N]     = reg + rank;
        out[N + 1] = reg;
        out[N + 2] = rank;
    }
}

extern "C" void kernel_launch(void* const* d_in, const int* in_sizes, int n_in,
                              void* d_out, int out_size)
{
    const float*    feature = (const float*)d_in[0];
    const float*    ret     = (const float*)d_in[1];
    const unsigned* mask    = (const unsigned*)d_in[2];
    const float*    Wih     = (const float*)d_in[3];
    const float*    Whh     = (const float*)d_in[4];
    const float*    bih     = (const float*)d_in[5];
    const float*    bhh     = (const float*)d_in[6];
    const float*    Wd      = (const float*)d_in[7];
    const float*    bd      = (const float*)d_in[8];
    float* out = (float*)d_out;

    const int N = in_sizes[1];                 // 4096
    const int T = in_sizes[0] / (N * F);       // 512

    const int grid = (N + BS - 1) / BS;        // 293
    lstm_kernel<<<grid, TPB>>>(feature, Wih, Whh, bih, bhh, Wd, bd, out, N, T);
    pair_kernel<<<RB, 256>>>(out, ret, mask, N);
    finalize_kernel<<<1, 32>>>(out, N);
}

// round 4
// speedup vs baseline: 1.3662x; 1.3662x over previous
#include <cuda_runtime.h>

#define H   64
#define G   256    // 4*H
#define F   5
#define BS  14     // samples per block -> grid=293 ~= 2*148 CTA slots, single balanced wave
#define TPB 256    // one thread per gate row
#define RB  128
#define NCELL (BS * H)   // 896 cells per block

__device__ float g_rank_part[RB];
__device__ float g_reg_part[2];

// MUFU.TANH (1 MUFU op)
__device__ __forceinline__ float tanh_hw(float x) {
    float y;
    asm("tanh.approx.f32 %0, %1;" : "=f"(y) : "f"(x));
    return y;
}
__device__ __forceinline__ float sig_hw(float x) {
    return fmaf(tanh_hw(0.5f * x), 0.5f, 0.5f);
}

// packed dual-FMA (sm_103a FFMA2), k-packed pairs
__device__ __forceinline__ unsigned long long fma2(unsigned long long a,
                                                   unsigned long long b,
                                                   unsigned long long c) {
    unsigned long long d;
    asm("fma.rn.f32x2 %0, %1, %2, %3;" : "=l"(d) : "l"(a), "l"(b), "l"(c));
    return d;
}
__device__ __forceinline__ float f2lo(unsigned long long v) {
    return __uint_as_float((unsigned)(v & 0xffffffffULL));
}
__device__ __forceinline__ float f2hi(unsigned long long v) {
    return __uint_as_float((unsigned)(v >> 32));
}

__global__ __launch_bounds__(TPB, 2)
void lstm_kernel(const float* __restrict__ feature,
                 const float* __restrict__ Wih, const float* __restrict__ Whh,
                 const float* __restrict__ bih, const float* __restrict__ bhh,
                 const float* __restrict__ Wd,  const float* __restrict__ bd,
                 float* __restrict__ pred, int N, int T)
{
    const int r  = threadIdx.x;          // gate row 0..255 (i,f,g,o blocks of 64)
    const int n0 = blockIdx.x * BS;

    // Per-thread resident Whh row, k-packed f32x2 (64 regs)
    unsigned long long wh2[H / 2];
    {
        const ulonglong2* w4 = (const ulonglong2*)(Whh + r * H);
#pragma unroll
        for (int q = 0; q < H / 4; q++) {
            ulonglong2 v = w4[q];
            wh2[2 * q + 0] = v.x;
            wh2[2 * q + 1] = v.y;
        }
    }
    float wi[F];
#pragma unroll
    for (int f = 0; f < F; f++) wi[f] = Wih[r * F + f];
    const float bias = bih[r] + bhh[r];

    __shared__ __align__(16) float h_sm[BS][H];
    __shared__ float g_sm[BS][G];
    __shared__ float x_sm[2][BS][F];

    float c_reg[4];                       // 3 full cells + optional 4th (r<128)
#pragma unroll
    for (int u = 0; u < 4; u++) c_reg[u] = 0.f;
#pragma unroll
    for (int u = 0; u < 3; u++) {
        int idx = r + TPB * u;
        h_sm[idx >> 6][idx & 63] = 0.f;
    }
    if (r < NCELL - 3 * TPB) {            // remainder 128 cells
        int idx = 3 * TPB + r;
        h_sm[idx >> 6][idx & 63] = 0.f;
    }
    if (r < BS * F) { int s = r / F, f = r % F; x_sm[0][s][f] = 0.f; x_sm[1][s][f] = 0.f; }
    __syncthreads();
    if (r < BS * F) {
        int s = r / F, f = r % F;
        if (n0 + s < N) x_sm[0][s][f] = feature[(size_t)(n0 + s) * T * F + f];
    }
    __syncthreads();

    for (int t = 0; t < T; t++) {
        const int buf = t & 1;

        // ---- phase 1: gate = bias + Whh_row . h + Wih_row . x (k-packed FFMA2)
#pragma unroll 2
        for (int s = 0; s < BS; s++) {
            unsigned long long acc = 0ULL;
            const ulonglong2* h2 = (const ulonglong2*)h_sm[s];   // uniform -> broadcast
#pragma unroll
            for (int q = 0; q < H / 4; q++) {
                ulonglong2 hv = h2[q];
                acc = fma2(wh2[2 * q + 0], hv.x, acc);
                acc = fma2(wh2[2 * q + 1], hv.y, acc);
            }
            float a = f2lo(acc) + f2hi(acc) + bias;
#pragma unroll
            for (int f = 0; f < F; f++) a = fmaf(wi[f], x_sm[buf][s][f], a);
            g_sm[s][r] = a;
        }
        __syncthreads();

        // ---- prefetch x for t+1
        if (t + 1 < T && r < BS * F) {
            int s = r / F, f = r % F;
            if (n0 + s < N)
                x_sm[buf ^ 1][s][f] =
                    feature[(size_t)(n0 + s) * T * F + (size_t)(t + 1) * F + f];
        }

        // ---- phase 2: LSTM cell update (gate order i,f,g,o), 896 cells
#pragma unroll
        for (int u = 0; u < 3; u++) {
            int idx = r + TPB * u;
            int s = idx >> 6, j = idx & 63;
            float ig = sig_hw(g_sm[s][j]);
            float fg = sig_hw(g_sm[s][H + j]);
            float gg = tanh_hw(g_sm[s][2 * H + j]);
            float og = sig_hw(g_sm[s][3 * H + j]);
            float c  = fg * c_reg[u] + ig * gg;
            c_reg[u] = c;
            h_sm[s][j] = og * tanh_hw(c);
        }
        if (r < NCELL - 3 * TPB) {
            int idx = 3 * TPB + r;
            int s = idx >> 6, j = idx & 63;
            float ig = sig_hw(g_sm[s][j]);
            float fg = sig_hw(g_sm[s][H + j]);
            float gg = tanh_hw(g_sm[s][2 * H + j]);
            float og = sig_hw(g_sm[s][3 * H + j]);
            float c  = fg * c_reg[3] + ig * gg;
            c_reg[3] = c;
            h_sm[s][j] = og * tanh_hw(c);
        }
        __syncthreads();
    }

    // ---- head: pred = leaky_relu(h . Wd + bd, 0.2); warps stride samples
    int w = r >> 5, lane = r & 31;
    for (int s = w; s < BS; s += TPB / 32) {
        if (n0 + s < N) {
            float p = h_sm[s][lane] * Wd[lane] + h_sm[s][lane + 32] * Wd[lane + 32];
#pragma unroll
            for (int off = 16; off; off >>= 1) p += __shfl_down_sync(0xffffffffu, p, off);
            if (lane == 0) {
                p += bd[0];
                p = p > 0.f ? p : 0.2f * p;
                pred[n0 + s] = p;
            }
        }
    }
}

// Pairwise rank loss partials + masked MSE partials (deterministic, no atomics).
__global__ void pair_kernel(const float* __restrict__ pred, const float* __restrict__ ret,
                            const unsigned* __restrict__ mask, int N)
{
    __shared__ float p_sm[4096];
    __shared__ float t_sm[4096];
    __shared__ unsigned char m_sm[4096];
    __shared__ float red[256];
    const int tid = threadIdx.x;

    for (int n = tid; n < N; n += blockDim.x) {
        p_sm[n] = pred[n];
        t_sm[n] = ret[n];
        m_sm[n] = (mask[n] != 0u) ? 1 : 0;
    }
    __syncthreads();

    float rsum = 0.f;
    for (int i = blockIdx.x; i < N; i += gridDim.x) {
        if (!m_sm[i]) continue;
        float pi = p_sm[i], gi = t_sm[i];
        for (int j = tid; j < N; j += blockDim.x) {
            float v = -(p_sm[j] - pi) * (t_sm[j] - gi);
            v = fmaxf(v, 0.f);
            rsum += v * (float)m_sm[j];
        }
    }
    red[tid] = rsum;
    __syncthreads();
    for (int s = 128; s; s >>= 1) { if (tid < s) red[tid] += red[tid + s]; __syncthreads(); }
    if (tid == 0) g_rank_part[blockIdx.x] = red[0];

    if (blockIdx.x == 0) {
        float ssq = 0.f, sm = 0.f;
        for (int n = tid; n < N; n += blockDim.x) {
            float m = (float)m_sm[n];
            float d = p_sm[n] - t_sm[n];
            ssq += d * d * m;
            sm  += m;
        }
        __syncthreads();
        red[tid] = ssq; __syncthreads();
        for (int s = 128; s; s >>= 1) { if (tid < s) red[tid] += red[tid + s]; __syncthreads(); }
        if (tid == 0) g_reg_part[0] = red[0];
        __syncthreads();
        red[tid] = sm; __syncthreads();
        for (int s = 128; s; s >>= 1) { if (tid < s) red[tid] += red[tid + s]; __syncthreads(); }
        if (tid == 0) g_reg_part[1] = red[0];
    }
}

__global__ void finalize_kernel(float* __restrict__ out, int N)
{
    if (threadIdx.x == 0 && blockIdx.x == 0) {
        float srank = 0.f;
        for (int b = 0; b < RB; b++) srank += g_rank_part[b];
        float reg  = g_reg_part[0] / (g_reg_part[1] + 1e-8f);
        float rank = srank / ((float)N * (float)N);
        out[N]     = reg + rank;
        out[N + 1] = reg;
        out[N + 2] = rank;
    }
}

extern "C" void kernel_launch(void* const* d_in, const int* in_sizes, int n_in,
                              void* d_out, int out_size)
{
    const float*    feature = (const float*)d_in[0];
    const float*    ret     = (const float*)d_in[1];
    const unsigned* mask    = (const unsigned*)d_in[2];
    const float*    Wih     = (const float*)d_in[3];
    const float*    Whh     = (const float*)d_in[4];
    const float*    bih     = (const float*)d_in[5];
    const float*    bhh     = (const float*)d_in[6];
    const float*    Wd      = (const float*)d_in[7];
    const float*    bd      = (const float*)d_in[8];
    float* out = (float*)d_out;

    const int N = in_sizes[1];                 // 4096
    const int T = in_sizes[0] / (N * F);       // 512

    const int grid = (N + BS - 1) / BS;        // 293
    lstm_kernel<<<grid, TPB>>>(feature, Wih, Whh, bih, bhh, Wd, bd, out, N, T);
    pair_kernel<<<RB, 256>>>(out, ret, mask, N);
    finalize_kernel<<<1, 32>>>(out, N);
}